// round 3
// baseline (speedup 1.0000x reference)
#include <cuda_runtime.h>
#include <math.h>

// ---------------------------------------------------------------------------
// ClusterAttn: b=1, D=32, H=128, W=128, C=96, P=4, FEAD=64, K=64
// Pipeline:
//  k1  : dwc stage1  y_t[p] = dot_c(x[p,:], w[:,t])   (27 maps, f32x2 FMA)
//  k2  : dwc stage2  dnx gather + pool to fea tokens + colwise sum-of-squares
//  k3  : inv column norms
//  k4a : normalize fea in place
//  k4b : logits = fea @ centroids^T, exp
//  k4c : per-cluster column sums (softmax-over-N denominator)
//  k5  : M = E^T @ fea  -> new_centroids = M / colsum
//  k6  : kv = newc @ kv_w^T + kv_b -> k_, v_
//  k7a : q = fea @ q_w^T + q_b
//  k7b1: attn logits = q @ k^T / 8
//  k7b2: row softmax
//  k7c : out = attn @ v
//  k8  : scatter tokens back to 1-channel volume o1
//  k9  : upc conv (1->96) + bias + residual x, channel-pair f32x2
// ---------------------------------------------------------------------------

#define DD 32
#define HH 128
#define WW 128
#define NP (DD*HH*WW)      // 524288 voxels
#define CC 96
#define NT 8192            // tokens
#define FE 64              // FEAD
#define KK 64              // clusters

// ------------------------- scratch (device globals) -------------------------
__device__ __align__(256) float g_y[27*NP];        // 56.6 MB
__device__ __align__(256) float g_fea[NT*FE];
__device__ __align__(256) float g_expl[NT*KK];
__device__ __align__(256) float g_q[NT*FE];
__device__ __align__(256) float g_attn[NT*KK];
__device__ __align__(256) float g_out[NT*FE];
__device__ __align__(256) float g_o1[NP];
__device__ __align__(256) float g_ssq[FE];
__device__ __align__(256) float g_inv[FE];
__device__ __align__(256) float g_colsum[KK];
__device__ __align__(256) float g_newc[KK*FE];
__device__ __align__(256) float g_k[KK*FE];
__device__ __align__(256) float g_v[KK*FE];

// ------------------------- f32x2 packed helpers -----------------------------
using u64 = unsigned long long;
__device__ __forceinline__ u64 pk2(float a, float b) {
    u64 r; asm("mov.b64 %0,{%1,%2};" : "=l"(r) : "f"(a), "f"(b)); return r;
}
__device__ __forceinline__ float2 upk2(u64 v) {
    float2 r; asm("mov.b64 {%0,%1},%2;" : "=f"(r.x), "=f"(r.y) : "l"(v)); return r;
}
__device__ __forceinline__ u64 ffma2(u64 a, u64 b, u64 c) {
    u64 d; asm("fma.rn.f32x2 %0,%1,%2,%3;" : "=l"(d) : "l"(a), "l"(b), "l"(c)); return d;
}

// ------------------------- k0: init small accumulators ----------------------
__global__ void k0_init() {
    int t = threadIdx.x;
    if (t < FE) g_ssq[t] = 0.f;
}

// ------------------------- k1: dwc stage1 -----------------------------------
// Each thread: 2 consecutive voxels packed in f32x2. y[t][p] = sum_c x[p,c]*w[c,t]
__global__ __launch_bounds__(256) void k1_dwc1(const float* __restrict__ x,
                                               const float* __restrict__ dwc_w) {
    __shared__ u64 w2[CC*27];
    for (int i = threadIdx.x; i < CC*27; i += 256) { float v = dwc_w[i]; w2[i] = pk2(v, v); }
    __syncthreads();

    int pr = blockIdx.x*256 + threadIdx.x;       // voxel pair id, 0..NP/2-1
    const float* xa = x + (size_t)pr * 192;      // 2 voxels * 96 ch

    u64 acc[27];
#pragma unroll
    for (int t = 0; t < 27; t++) acc[t] = 0ull;

    for (int c = 0; c < CC; c += 4) {
        float4 a4 = *reinterpret_cast<const float4*>(xa + c);
        float4 b4 = *reinterpret_cast<const float4*>(xa + 96 + c);
        u64 p0 = pk2(a4.x, b4.x), p1 = pk2(a4.y, b4.y);
        u64 p2 = pk2(a4.z, b4.z), p3 = pk2(a4.w, b4.w);
        const u64* wc = w2 + c*27;
#pragma unroll
        for (int t = 0; t < 27; t++) {
            acc[t] = ffma2(p0, wc[t],      acc[t]);
            acc[t] = ffma2(p1, wc[27+t],   acc[t]);
            acc[t] = ffma2(p2, wc[54+t],   acc[t]);
            acc[t] = ffma2(p3, wc[81+t],   acc[t]);
        }
    }
#pragma unroll
    for (int t = 0; t < 27; t++) {
        float2 v = upk2(acc[t]);
        *reinterpret_cast<float2*>(g_y + (size_t)t*NP + pr*2) = v;
    }
}

// ------------------------- k2: gather + pool to fea + ssq -------------------
__global__ __launch_bounds__(256) void k2_gather(const float* __restrict__ dwc_b) {
    __shared__ float ssq_s[FE];
    if (threadIdx.x < FE) ssq_s[threadIdx.x] = 0.f;
    __syncthreads();

    int idx = blockIdx.x*256 + threadIdx.x;      // == n*64 + f  (NP total)
    int n = idx >> 6, f = idx & 63;
    int xb = n & 31, yb = (n >> 5) & 31, zb = n >> 10;
    int px = f & 3, py = (f >> 2) & 3, pz = f >> 4;
    int z = zb*4 + pz, y = yb*4 + py, xx = xb*4 + px;

    float v = dwc_b[0];
#pragma unroll
    for (int kz = 0; kz < 3; kz++) {
        int zz = z + kz - 1; if ((unsigned)zz >= DD) continue;
#pragma unroll
        for (int ky = 0; ky < 3; ky++) {
            int yy = y + ky - 1; if ((unsigned)yy >= HH) continue;
#pragma unroll
            for (int kx = 0; kx < 3; kx++) {
                int xc = xx + kx - 1; if ((unsigned)xc >= WW) continue;
                int t = kz*9 + ky*3 + kx;
                v += g_y[(size_t)t*NP + (zz*HH + yy)*WW + xc];
            }
        }
    }
    g_fea[idx] = v;
    atomicAdd(&ssq_s[f], v*v);
    __syncthreads();
    if (threadIdx.x < FE) atomicAdd(&g_ssq[threadIdx.x], ssq_s[threadIdx.x]);
}

// ------------------------- k3: inverse column norms -------------------------
__global__ void k3_inv() {
    int f = threadIdx.x;
    if (f < FE) g_inv[f] = 1.f / fmaxf(sqrtf(g_ssq[f]), 1e-12f);
}

// ------------------------- k4a: normalize fea in place ----------------------
__global__ void k4a_norm() {
    int i = blockIdx.x*256 + threadIdx.x;        // float4 index, NT*FE/4 total
    float4* p = reinterpret_cast<float4*>(g_fea);
    float4 v = p[i];
    int f0 = (i*4) & 63;
    v.x *= g_inv[f0]; v.y *= g_inv[f0+1]; v.z *= g_inv[f0+2]; v.w *= g_inv[f0+3];
    p[i] = v;
}

// ------------------------- k4b: logits + exp --------------------------------
__global__ __launch_bounds__(256) void k4b_logits(const float* __restrict__ cen) {
    __shared__ float4 cen_s[KK*16];
    for (int i = threadIdx.x; i < KK*16; i += 256)
        cen_s[i] = reinterpret_cast<const float4*>(cen)[i];
    __syncthreads();

    int idx = blockIdx.x*256 + threadIdx.x;      // 32768: (n, c-quarter)
    int n = idx >> 2, c0 = (idx & 3) * 16;
    float fr[FE];
    const float4* frp = reinterpret_cast<const float4*>(g_fea + n*FE);
#pragma unroll
    for (int f4 = 0; f4 < 16; f4++) {
        float4 v = frp[f4];
        fr[f4*4] = v.x; fr[f4*4+1] = v.y; fr[f4*4+2] = v.z; fr[f4*4+3] = v.w;
    }
#pragma unroll
    for (int cc = 0; cc < 16; cc++) {
        int c = c0 + cc;
        const float4* cr = cen_s + c*16;
        float l = 0.f;
#pragma unroll
        for (int f4 = 0; f4 < 16; f4++) {
            float4 w = cr[f4];
            l += fr[f4*4]*w.x + fr[f4*4+1]*w.y + fr[f4*4+2]*w.z + fr[f4*4+3]*w.w;
        }
        g_expl[n*KK + c] = __expf(l);
    }
}

// ------------------------- k4c: per-cluster column sums ---------------------
__global__ void k4c_colsum() {                   // grid 64, block 256
    int c = blockIdx.x;
    float s = 0.f;
    for (int n = threadIdx.x; n < NT; n += 256) s += g_expl[n*KK + c];
    __shared__ float sm[8];
    int lane = threadIdx.x & 31, w = threadIdx.x >> 5;
#pragma unroll
    for (int o = 16; o > 0; o >>= 1) s += __shfl_down_sync(0xffffffffu, s, o);
    if (lane == 0) sm[w] = s;
    __syncthreads();
    if (threadIdx.x == 0) {
        float t = 0.f;
#pragma unroll
        for (int i = 0; i < 8; i++) t += sm[i];
        g_colsum[c] = t;
    }
}

// ------------------------- k5: new_centroids = (E^T @ fea)/colsum -----------
__global__ __launch_bounds__(256) void k5_newc() {   // grid 64 (cluster c)
    int c = blockIdx.x;
    float acc[FE];
#pragma unroll
    for (int f = 0; f < FE; f++) acc[f] = 0.f;
    for (int n = threadIdx.x; n < NT; n += 256) {
        float e = g_expl[n*KK + c];
        const float4* fr = reinterpret_cast<const float4*>(g_fea + n*FE);
#pragma unroll
        for (int f4 = 0; f4 < 16; f4++) {
            float4 v = fr[f4];
            acc[f4*4]   += e*v.x; acc[f4*4+1] += e*v.y;
            acc[f4*4+2] += e*v.z; acc[f4*4+3] += e*v.w;
        }
    }
    __shared__ float red[FE];
    if (threadIdx.x < FE) red[threadIdx.x] = 0.f;
    __syncthreads();
    int lane = threadIdx.x & 31;
#pragma unroll
    for (int f = 0; f < FE; f++) {
        float r = acc[f];
#pragma unroll
        for (int o = 16; o > 0; o >>= 1) r += __shfl_down_sync(0xffffffffu, r, o);
        if (lane == 0) atomicAdd(&red[f], r);
    }
    __syncthreads();
    if (threadIdx.x < FE)
        g_newc[c*FE + threadIdx.x] = red[threadIdx.x] / g_colsum[c];
}

// ------------------------- k6: kv projection --------------------------------
__global__ void k6_kv(const float* __restrict__ kv_w, const float* __restrict__ kv_b) {
    __shared__ float nc_s[FE];                   // grid 64 (c), block 128 (j)
    int c = blockIdx.x, j = threadIdx.x;
    if (j < FE) nc_s[j] = g_newc[c*FE + j];
    __syncthreads();
    float acc = kv_b[j];
    const float* wr = kv_w + j*FE;
#pragma unroll
    for (int f = 0; f < FE; f++) acc += nc_s[f] * wr[f];
    if (j < 64) g_k[c*FE + j] = acc;
    else        g_v[c*FE + (j - 64)] = acc;
}

// ------------------------- k7a: q projection --------------------------------
__global__ __launch_bounds__(256) void k7a_q(const float* __restrict__ qw,
                                             const float* __restrict__ qb) {
    __shared__ float4 qw_s[FE*16];
    __shared__ float qb_s[FE];
    for (int i = threadIdx.x; i < FE*16; i += 256)
        qw_s[i] = reinterpret_cast<const float4*>(qw)[i];
    if (threadIdx.x < FE) qb_s[threadIdx.x] = qb[threadIdx.x];
    __syncthreads();

    int idx = blockIdx.x*256 + threadIdx.x;
    int n = idx >> 2, j0 = (idx & 3) * 16;
    float fr[FE];
    const float4* frp = reinterpret_cast<const float4*>(g_fea + n*FE);
#pragma unroll
    for (int f4 = 0; f4 < 16; f4++) {
        float4 v = frp[f4];
        fr[f4*4] = v.x; fr[f4*4+1] = v.y; fr[f4*4+2] = v.z; fr[f4*4+3] = v.w;
    }
    for (int jj = 0; jj < 16; jj++) {
        int j = j0 + jj;
        float acc = qb_s[j];
        const float4* wr = qw_s + j*16;
#pragma unroll
        for (int f4 = 0; f4 < 16; f4++) {
            float4 w = wr[f4];
            acc += fr[f4*4]*w.x + fr[f4*4+1]*w.y + fr[f4*4+2]*w.z + fr[f4*4+3]*w.w;
        }
        g_q[n*FE + j] = acc;
    }
}

// ------------------------- k7b1: attention logits ---------------------------
__global__ __launch_bounds__(256) void k7b1_al() {
    __shared__ float4 k_s[KK*16];
    for (int i = threadIdx.x; i < KK*16; i += 256)
        k_s[i] = reinterpret_cast<const float4*>(g_k)[i];
    __syncthreads();

    int idx = blockIdx.x*256 + threadIdx.x;
    int n = idx >> 2, c0 = (idx & 3) * 16;
    float qr[FE];
    const float4* qp = reinterpret_cast<const float4*>(g_q + n*FE);
#pragma unroll
    for (int f4 = 0; f4 < 16; f4++) {
        float4 v = qp[f4];
        qr[f4*4] = v.x; qr[f4*4+1] = v.y; qr[f4*4+2] = v.z; qr[f4*4+3] = v.w;
    }
    for (int cc = 0; cc < 16; cc++) {
        int c = c0 + cc;
        const float4* kr = k_s + c*16;
        float l = 0.f;
#pragma unroll
        for (int f4 = 0; f4 < 16; f4++) {
            float4 w = kr[f4];
            l += qr[f4*4]*w.x + qr[f4*4+1]*w.y + qr[f4*4+2]*w.z + qr[f4*4+3]*w.w;
        }
        g_attn[n*KK + c] = l * 0.125f;
    }
}

// ------------------------- k7b2: row softmax --------------------------------
__global__ void k7b2_sm() {                      // grid 32, block 256
    int n = blockIdx.x*256 + threadIdx.x;
    float a[KK];
    float4* ap = reinterpret_cast<float4*>(g_attn + n*KK);
    float m = -1e30f;
#pragma unroll
    for (int i = 0; i < 16; i++) {
        float4 v = ap[i];
        a[i*4] = v.x; a[i*4+1] = v.y; a[i*4+2] = v.z; a[i*4+3] = v.w;
        m = fmaxf(m, fmaxf(fmaxf(v.x, v.y), fmaxf(v.z, v.w)));
    }
    float s = 0.f;
#pragma unroll
    for (int c = 0; c < KK; c++) { a[c] = __expf(a[c] - m); s += a[c]; }
    float si = 1.f / s;
#pragma unroll
    for (int i = 0; i < 16; i++)
        ap[i] = make_float4(a[i*4]*si, a[i*4+1]*si, a[i*4+2]*si, a[i*4+3]*si);
}

// ------------------------- k7c: out = attn @ v ------------------------------
__global__ __launch_bounds__(256) void k7c_out() {
    __shared__ float4 v_s[KK*16];
    for (int i = threadIdx.x; i < KK*16; i += 256)
        v_s[i] = reinterpret_cast<const float4*>(g_v)[i];
    __syncthreads();

    int idx = blockIdx.x*256 + threadIdx.x;
    int n = idx >> 2, f0 = (idx & 3) * 16;
    float a[KK];
    const float4* ap = reinterpret_cast<const float4*>(g_attn + n*KK);
#pragma unroll
    for (int i = 0; i < 16; i++) {
        float4 v = ap[i];
        a[i*4] = v.x; a[i*4+1] = v.y; a[i*4+2] = v.z; a[i*4+3] = v.w;
    }
    float acc[16];
#pragma unroll
    for (int k = 0; k < 16; k++) acc[k] = 0.f;
    for (int c = 0; c < KK; c++) {
        float ac = a[c];
        const float4* vr = v_s + c*16 + (f0 >> 2);
#pragma unroll
        for (int k = 0; k < 4; k++) {
            float4 v = vr[k];
            acc[k*4]   += ac*v.x; acc[k*4+1] += ac*v.y;
            acc[k*4+2] += ac*v.z; acc[k*4+3] += ac*v.w;
        }
    }
    float4* op = reinterpret_cast<float4*>(g_out + n*FE + f0);
#pragma unroll
    for (int k = 0; k < 4; k++)
        op[k] = make_float4(acc[k*4], acc[k*4+1], acc[k*4+2], acc[k*4+3]);
}

// ------------------------- k8: scatter tokens to volume ---------------------
__global__ void k8_scatter() {
    int idx = blockIdx.x*256 + threadIdx.x;
    int n = idx >> 6, f = idx & 63;
    int xb = n & 31, yb = (n >> 5) & 31, zb = n >> 10;
    int px = f & 3, py = (f >> 2) & 3, pz = f >> 4;
    int p = ((zb*4 + pz)*HH + (yb*4 + py))*WW + (xb*4 + px);
    g_o1[p] = g_out[idx];
}

// ------------------------- k9: upc conv + bias + residual -------------------
__global__ __launch_bounds__(256) void k9_upc(const float* __restrict__ x,
                                              const float* __restrict__ uw,
                                              const float* __restrict__ ub,
                                              float* __restrict__ out) {
    __shared__ u64 w2[48*27];
    __shared__ float2 b2[48];
    for (int i = threadIdx.x; i < 48*27; i += 256) {
        int cp = i / 27, t = i % 27;
        w2[i] = pk2(uw[(2*cp)*27 + t], uw[(2*cp + 1)*27 + t]);
    }
    if (threadIdx.x < 48)
        b2[threadIdx.x] = make_float2(ub[2*threadIdx.x], ub[2*threadIdx.x + 1]);
    __syncthreads();

    int p = blockIdx.x*256 + threadIdx.x;
    int z = p >> 14, y = (p >> 7) & 127, xx = p & 127;

    u64 o2[27];
#pragma unroll
    for (int kz = 0; kz < 3; kz++)
#pragma unroll
    for (int ky = 0; ky < 3; ky++)
#pragma unroll
    for (int kx = 0; kx < 3; kx++) {
        int zz = z + kz - 1, yy = y + ky - 1, xc = xx + kx - 1;
        float v = 0.f;
        if ((unsigned)zz < DD && (unsigned)yy < HH && (unsigned)xc < WW)
            v = g_o1[(zz*HH + yy)*WW + xc];
        o2[kz*9 + ky*3 + kx] = pk2(v, v);
    }

    const float2* xr = reinterpret_cast<const float2*>(x + (size_t)p*CC);
    float2* orow = reinterpret_cast<float2*>(out + (size_t)p*CC);
    for (int cp = 0; cp < 48; cp++) {
        float2 xv = xr[cp];
        float2 bb = b2[cp];
        u64 acc = pk2(xv.x + bb.x, xv.y + bb.y);
        const u64* wr = w2 + cp*27;
#pragma unroll
        for (int t = 0; t < 27; t++) acc = ffma2(o2[t], wr[t], acc);
        float2 r = upk2(acc);
        orow[cp] = r;
    }
}

// ------------------------- launch --------------------------------------------
extern "C" void kernel_launch(void* const* d_in, const int* in_sizes, int n_in,
                              void* d_out, int out_size) {
    const float* x     = (const float*)d_in[0];
    const float* cen   = (const float*)d_in[1];
    const float* dwc_w = (const float*)d_in[2];
    const float* dwc_b = (const float*)d_in[3];
    const float* upc_w = (const float*)d_in[4];
    const float* upc_b = (const float*)d_in[5];
    const float* q_w   = (const float*)d_in[6];
    const float* q_b   = (const float*)d_in[7];
    const float* kv_w  = (const float*)d_in[8];
    const float* kv_b  = (const float*)d_in[9];
    float* out = (float*)d_out;

    k0_init   <<<1, 64>>>();
    k1_dwc1   <<<NP/2/256, 256>>>(x, dwc_w);
    k2_gather <<<NP/256,   256>>>(dwc_b);
    k3_inv    <<<1, 64>>>();
    k4a_norm  <<<(NT*FE/4)/256, 256>>>();
    k4b_logits<<<(NT*4)/256, 256>>>(cen);
    k4c_colsum<<<KK, 256>>>();
    k5_newc   <<<KK, 256>>>();
    k6_kv     <<<KK, 128>>>(kv_w, kv_b);
    k7a_q     <<<(NT*4)/256, 256>>>(q_w, q_b);
    k7b1_al   <<<(NT*4)/256, 256>>>();
    k7b2_sm   <<<NT/256, 256>>>();
    k7c_out   <<<(NT*4)/256, 256>>>();
    k8_scatter<<<NP/256, 256>>>();
    k9_upc    <<<NP/256, 256>>>(x, upc_w, upc_b, out);
}